// round 14
// baseline (speedup 1.0000x reference)
#include <cuda_runtime.h>
#include <cuda_bf16.h>
#include <cstdint>

// ----------------------------------------------------------------------------
// VolumetricSampler: 16384 rays x 512 steps occupancy-grid sampling.
// Round 13: the 32MB ray_indices plane (occ/geometry-independent) moves from
// the DRAM-saturated sampler into the latency-bound pack kernel (idle BW):
// each pack thread owns 64 ray-aligned segments -> 16 constant STG.128.
// Bit grid, fused partials, scan, __f*_rn predicate math all unchanged
// (rel_err 0.0 since R2).
//
// Bit mapping (pack/lookup): voxel v ->
//   word = v >> 5,  bit = ((v & 3) << 3) | ((v >> 2) & 7)
//
// Output layout (float32):
//   origins     [8388608, 3]  -> [0,        25165824)
//   dirs        [8388608, 3]  -> [25165824, 50331648)
//   s_flat      [8388608]     -> [50331648, 58720256)
//   e_flat      [8388608]     -> [58720256, 67108864)
//   packed_info [16384, 2]    -> [67108864, 67141632)
//   ray_indices [8388608]     -> [67141632, 75530240)
//   mask        [8388608]     -> [75530240, 83918848)
// ----------------------------------------------------------------------------

#define N_RAYS     16384
#define MAX_STEPS  512
#define GRID_R     128
#define NEAR_F     0.05f
#define FAR_F      3.0f

static __device__ __forceinline__ float step_size() {
    return (float)((3.0 - 0.05) / 512.0);   // fp32-rounded STEP, matches jnp
}

#define OFF_ORIG   0
#define OFF_DIR    25165824
#define OFF_S      50331648
#define OFF_E      58720256
#define OFF_PK     67108864
#define OFF_RI     67141632
#define OFF_MASK   75530240

#define N_VOXELS   (GRID_R * GRID_R * GRID_R)   // 2,097,152
#define N_WORDS    (N_VOXELS / 32)              // 65,536
#define SCAN_BLOCKS 64

__device__ __align__(16) int      g_counts[N_RAYS];
__device__ __align__(16) int      g_partials[SCAN_BLOCKS];
__device__ __align__(16) unsigned g_bits[N_WORDS];

// exact power of two (positive, normal): mantissa bits all zero
static __device__ __forceinline__ bool is_pow2f(float e) {
    const unsigned u = __float_as_uint(e);
    return ((u & 0x007FFFFFu) == 0u) && e > 0.0f;
}

// --- prep: pack bit grid (16 voxels/thread, MLP=4) + write the RI plane ---
// Thread t (131072 total) also owns segments [64t, 64t+64), all in ray t>>3,
// so the ray_indices value is one constant -> 16 STG.128 of idle-BW stores.
__global__ void __launch_bounds__(256)
pack_kernel(const int* __restrict__ occ, float* __restrict__ out)
{
    const int tid   = threadIdx.x;
    const int lane  = tid & 31;
    const int t     = blockIdx.x * 256 + tid;            // global thread id
    const int warpW = t >> 5;                            // global warp id
    const int4* base = (const int4*)occ;

    int4 v[4];
    #pragma unroll
    for (int j = 0; j < 4; j++)
        v[j] = __ldcs(base + (warpW << 7) + (j << 5) + lane);

    // RI plane: 64 consecutive floats of (float)(t >> 3), ray-aligned
    {
        const float rif = (float)(t >> 3);
        const float4 rv = make_float4(rif, rif, rif, rif);
        float* rb = out + OFF_RI + (t << 6);
        #pragma unroll
        for (int i = 0; i < 16; i++)
            __stcs((float4*)(rb + (i << 2)), rv);
    }

    #pragma unroll
    for (int j = 0; j < 4; j++) {
        const unsigned b0 = __ballot_sync(0xFFFFFFFFu, v[j].x != 0);
        const unsigned b1 = __ballot_sync(0xFFFFFFFFu, v[j].y != 0);
        const unsigned b2 = __ballot_sync(0xFFFFFFFFu, v[j].z != 0);
        const unsigned b3 = __ballot_sync(0xFFFFFFFFu, v[j].w != 0);
        if (lane < 4) {
            const int sh = lane << 3;
            const unsigned w = ((b0 >> sh) & 0xFFu)
                             | (((b1 >> sh) & 0xFFu) << 8)
                             | (((b2 >> sh) & 0xFFu) << 16)
                             | (((b3 >> sh) & 0xFFu) << 24);
            g_bits[(warpW << 4) + (j << 2) + lane] = w;
        }
    }

    if (blockIdx.x == 0 && tid < SCAN_BLOCKS)
        g_partials[tid] = 0;
}

// 256 threads/block, 2 rays/block, 128 threads/ray, 4 steps/thread.
__global__ void __launch_bounds__(256)
sampler_kernel(const float* __restrict__ rays_o,
               const float* __restrict__ rays_d,
               const float* __restrict__ aabb,
               float* __restrict__ out)
{
    const int tid = threadIdx.x;
    const int ray = blockIdx.x * 2 + (tid >> 7);
    const int q   = tid & 127;          // quad index within ray
    const int s0  = q << 2;             // first step of this thread's quad

    const float ox = rays_o[ray * 3 + 0];
    const float oy = rays_o[ray * 3 + 1];
    const float oz = rays_o[ray * 3 + 2];
    const float dx = rays_d[ray * 3 + 0];
    const float dy = rays_d[ray * 3 + 1];
    const float dz = rays_d[ray * 3 + 2];

    const float a0x = aabb[0], a0y = aabb[1], a0z = aabb[2];
    const float a1x = aabb[3], a1y = aabb[4], a1z = aabb[5];

    // --- ray/AABB intersection (separate rounding) ---
    const float sdx = (fabsf(dx) > 1e-10f) ? dx : 1e-10f;
    const float sdy = (fabsf(dy) > 1e-10f) ? dy : 1e-10f;
    const float sdz = (fabsf(dz) > 1e-10f) ? dz : 1e-10f;
    const float ix_ = __fdiv_rn(1.0f, sdx);
    const float iy_ = __fdiv_rn(1.0f, sdy);
    const float iz_ = __fdiv_rn(1.0f, sdz);

    const float t0x = __fmul_rn(__fsub_rn(a0x, ox), ix_);
    const float t1x = __fmul_rn(__fsub_rn(a1x, ox), ix_);
    const float t0y = __fmul_rn(__fsub_rn(a0y, oy), iy_);
    const float t1y = __fmul_rn(__fsub_rn(a1y, oy), iy_);
    const float t0z = __fmul_rn(__fsub_rn(a0z, oz), iz_);
    const float t1z = __fmul_rn(__fsub_rn(a1z, oz), iz_);

    const float tmin = fmaxf(fmaxf(fmaxf(fminf(t0x, t1x), fminf(t0y, t1y)),
                                   fminf(t0z, t1z)), NEAR_F);
    const float tmax = fminf(fminf(fminf(fmaxf(t0x, t1x), fmaxf(t0y, t1y)),
                                   fmaxf(t0z, t1z)), FAR_F);

    const float ex = __fsub_rn(a1x, a0x);
    const float ey = __fsub_rn(a1y, a0y);
    const float ez = __fsub_rn(a1z, a0z);
    const float STEPF = step_size();

    float st[4], en[4], m[4];
    float sx[4], sy[4], sz[4];
    bool  valid[4];
    int   occ_idx[4];
    bool  pre[4];

    // Pass 1a: positions
    float nx[4], ny[4], nz[4];
    #pragma unroll
    for (int k = 0; k < 4; k++) {
        const int step = s0 + k;
        st[k] = __fadd_rn(NEAR_F, __fmul_rn((float)step,       STEPF));
        en[k] = __fadd_rn(NEAR_F, __fmul_rn((float)(step + 1), STEPF));
        const float mid = __fmul_rn(0.5f, __fadd_rn(st[k], en[k]));
        nx[k] = __fsub_rn(__fadd_rn(ox, __fmul_rn(dx, mid)), a0x);
        ny[k] = __fsub_rn(__fadd_rn(oy, __fmul_rn(dy, mid)), a0y);
        nz[k] = __fsub_rn(__fadd_rn(oz, __fmul_rn(dz, mid)), a0z);
    }

    // Pass 1b: scale = n / extent; pow2 extents -> exact multiply path
    if (is_pow2f(ex) && is_pow2f(ey) && is_pow2f(ez)) {
        const float ivx = __fdiv_rn(1.0f, ex);   // exact
        const float ivy = __fdiv_rn(1.0f, ey);
        const float ivz = __fdiv_rn(1.0f, ez);
        #pragma unroll
        for (int k = 0; k < 4; k++) {
            sx[k] = __fmul_rn(nx[k], ivx);
            sy[k] = __fmul_rn(ny[k], ivy);
            sz[k] = __fmul_rn(nz[k], ivz);
        }
    } else {
        #pragma unroll
        for (int k = 0; k < 4; k++) {
            sx[k] = __fdiv_rn(nx[k], ex);
            sy[k] = __fdiv_rn(ny[k], ey);
            sz[k] = __fdiv_rn(nz[k], ez);
        }
    }

    // Pass 1c: predicates + voxel indices
    #pragma unroll
    for (int k = 0; k < 4; k++) {
        const bool inside = (sx[k] >= 0.0f) && (sx[k] < 1.0f) &&
                            (sy[k] >= 0.0f) && (sy[k] < 1.0f) &&
                            (sz[k] >= 0.0f) && (sz[k] < 1.0f);
        int gx = (int)__fmul_rn(sx[k], (float)GRID_R);
        int gy = (int)__fmul_rn(sy[k], (float)GRID_R);
        int gz = (int)__fmul_rn(sz[k], (float)GRID_R);
        gx = min(max(gx, 0), GRID_R - 1);
        gy = min(max(gy, 0), GRID_R - 1);
        gz = min(max(gz, 0), GRID_R - 1);
        occ_idx[k] = (gx << 14) + (gy << 7) + gz;
        pre[k] = (st[k] >= tmin) && (en[k] <= tmax) && inside;
    }

    // Pass 2: 4 independent bit-grid lookups (256KB array, L1-warm)
    unsigned wv[4];
    #pragma unroll
    for (int k = 0; k < 4; k++) wv[k] = g_bits[occ_idx[k] >> 5];
    int cnt = 0;
    #pragma unroll
    for (int k = 0; k < 4; k++) {
        const int bit = ((occ_idx[k] & 3) << 3) | ((occ_idx[k] >> 2) & 7);
        valid[k] = pre[k] && ((wv[k] >> bit) & 1u);
        m[k] = valid[k] ? 1.0f : 0.0f;
        cnt += valid[k] ? 1 : 0;
    }

    const int seg = (ray << 9) + s0;           // multiple of 4

    // --- vectorized streaming stores (RI plane handled by pack_kernel) ---
    __stcs((float4*)(out + OFF_S + seg),
           make_float4(valid[0] ? st[0] : 0.0f, valid[1] ? st[1] : 0.0f,
                       valid[2] ? st[2] : 0.0f, valid[3] ? st[3] : 0.0f));
    __stcs((float4*)(out + OFF_E + seg),
           make_float4(valid[0] ? en[0] : 0.0f, valid[1] ? en[1] : 0.0f,
                       valid[2] ? en[2] : 0.0f, valid[3] ? en[3] : 0.0f));
    __stcs((float4*)(out + OFF_MASK + seg), make_float4(m[0], m[1], m[2], m[3]));

    {
        const float x0 = __fmul_rn(ox, m[0]), y0 = __fmul_rn(oy, m[0]), z0 = __fmul_rn(oz, m[0]);
        const float x1 = __fmul_rn(ox, m[1]), y1 = __fmul_rn(oy, m[1]), z1 = __fmul_rn(oz, m[1]);
        const float x2 = __fmul_rn(ox, m[2]), y2 = __fmul_rn(oy, m[2]), z2 = __fmul_rn(oz, m[2]);
        const float x3 = __fmul_rn(ox, m[3]), y3 = __fmul_rn(oy, m[3]), z3 = __fmul_rn(oz, m[3]);
        float* ob = out + OFF_ORIG + seg * 3;
        __stcs((float4*)(ob + 0), make_float4(x0, y0, z0, x1));
        __stcs((float4*)(ob + 4), make_float4(y1, z1, x2, y2));
        __stcs((float4*)(ob + 8), make_float4(z2, x3, y3, z3));
    }
    {
        const float x0 = __fmul_rn(dx, m[0]), y0 = __fmul_rn(dy, m[0]), z0 = __fmul_rn(dz, m[0]);
        const float x1 = __fmul_rn(dx, m[1]), y1 = __fmul_rn(dy, m[1]), z1 = __fmul_rn(dz, m[1]);
        const float x2 = __fmul_rn(dx, m[2]), y2 = __fmul_rn(dy, m[2]), z2 = __fmul_rn(dz, m[2]);
        const float x3 = __fmul_rn(dx, m[3]), y3 = __fmul_rn(dy, m[3]), z3 = __fmul_rn(dz, m[3]);
        float* db = out + OFF_DIR + seg * 3;
        __stcs((float4*)(db + 0), make_float4(x0, y0, z0, x1));
        __stcs((float4*)(db + 4), make_float4(y1, z1, x2, y2));
        __stcs((float4*)(db + 8), make_float4(z2, x3, y3, z3));
    }

    // --- per-ray count: warp reduce + smem combine (4 warps per ray) ---
    const int wsum = __reduce_add_sync(0xFFFFFFFFu, cnt);
    __shared__ int ws[8];
    if ((tid & 31) == 0) ws[tid >> 5] = wsum;
    __syncthreads();
    if (q == 0) {
        const int b = (tid >> 7) * 4;
        const int c = ws[b] + ws[b + 1] + ws[b + 2] + ws[b + 3];
        g_counts[ray] = c;
        atomicAdd(&g_partials[ray >> 8], c);   // deterministic int sum
    }
}

// Final scan: 64 blocks x 256 threads, 1 ray/thread.
__global__ void __launch_bounds__(256)
scan_kernel(float* __restrict__ out)
{
    const int b    = blockIdx.x;
    const int tid  = threadIdx.x;
    const int lane = tid & 31;
    const int wid  = tid >> 5;          // 8 warps

    __shared__ int sh[8];
    __shared__ int s_pre;

    if (wid == 0) {
        int p = 0;
        if (lane      < b) p += g_partials[lane];
        if (lane + 32 < b) p += g_partials[lane + 32];
        p = __reduce_add_sync(0xFFFFFFFFu, p);
        if (lane == 0) s_pre = p;
    }

    const int ray = b * 256 + tid;
    const int cnt = g_counts[ray];

    int inc = cnt;
    #pragma unroll
    for (int d = 1; d < 32; d <<= 1) {
        int n = __shfl_up_sync(0xFFFFFFFFu, inc, d);
        if (lane >= d) inc += n;
    }
    if (lane == 31) sh[wid] = inc;
    __syncthreads();
    int woff = 0;
    #pragma unroll
    for (int i = 0; i < 8; i++) woff += (i < wid) ? sh[i] : 0;

    const int offset = s_pre + woff + (inc - cnt);   // exclusive

    *(float2*)(out + OFF_PK + ray * 2) = make_float2((float)offset, (float)cnt);
}

extern "C" void kernel_launch(void* const* d_in, const int* in_sizes, int n_in,
                              void* d_out, int out_size)
{
    const float* rays_o = (const float*)d_in[0];
    const float* rays_d = (const float*)d_in[1];
    const float* aabb   = (const float*)d_in[2];
    const int*   occ    = (const int*)  d_in[3];
    float* out = (float*)d_out;

    pack_kernel<<<N_VOXELS / 16 / 256, 256>>>(occ, out);
    sampler_kernel<<<N_RAYS / 2, 256>>>(rays_o, rays_d, aabb, out);
    scan_kernel<<<SCAN_BLOCKS, 256>>>(out);
}

// round 15
// speedup vs baseline: 1.1127x; 1.1127x over previous
#include <cuda_runtime.h>
#include <cuda_bf16.h>
#include <cstdint>

// ----------------------------------------------------------------------------
// VolumetricSampler: 16384 rays x 512 steps occupancy-grid sampling.
// Round 14: revert R13's RI move (mis-strided stores; and sampler proved only
// partially DRAM-bound). New lever: per-ray AABB intersection (tmin/tmax,
// ~85 instrs incl. 3 divides) was redundantly computed by all 128 threads of
// a ray -> hoisted into pack_kernel (one thread per ray), sampler loads a
// broadcast float2. Bit grid, fused partials, scan, __f*_rn math unchanged
// (rel_err 0.0 since R2).
//
// Bit mapping (pack/lookup): voxel v ->
//   word = v >> 5,  bit = ((v & 3) << 3) | ((v >> 2) & 7)
//
// Output layout (float32):
//   origins     [8388608, 3]  -> [0,        25165824)
//   dirs        [8388608, 3]  -> [25165824, 50331648)
//   s_flat      [8388608]     -> [50331648, 58720256)
//   e_flat      [8388608]     -> [58720256, 67108864)
//   packed_info [16384, 2]    -> [67108864, 67141632)
//   ray_indices [8388608]     -> [67141632, 75530240)
//   mask        [8388608]     -> [75530240, 83918848)
// ----------------------------------------------------------------------------

#define N_RAYS     16384
#define MAX_STEPS  512
#define GRID_R     128
#define NEAR_F     0.05f
#define FAR_F      3.0f

static __device__ __forceinline__ float step_size() {
    return (float)((3.0 - 0.05) / 512.0);   // fp32-rounded STEP, matches jnp
}

#define OFF_ORIG   0
#define OFF_DIR    25165824
#define OFF_S      50331648
#define OFF_E      58720256
#define OFF_PK     67108864
#define OFF_RI     67141632
#define OFF_MASK   75530240

#define N_VOXELS   (GRID_R * GRID_R * GRID_R)   // 2,097,152
#define N_WORDS    (N_VOXELS / 32)              // 65,536
#define SCAN_BLOCKS 64

__device__ __align__(16) int      g_counts[N_RAYS];
__device__ __align__(16) int      g_partials[SCAN_BLOCKS];
__device__ __align__(16) unsigned g_bits[N_WORDS];
__device__ __align__(16) float2   g_tminmax[N_RAYS];

// exact power of two (positive, normal): mantissa bits all zero
static __device__ __forceinline__ bool is_pow2f(float e) {
    const unsigned u = __float_as_uint(e);
    return ((u & 0x007FFFFFu) == 0u) && e > 0.0f;
}

// --- prep: bit grid (16 voxels/thread, MLP=4) + per-ray tmin/tmax ---
__global__ void __launch_bounds__(256)
pack_kernel(const int* __restrict__ occ,
            const float* __restrict__ rays_o,
            const float* __restrict__ rays_d,
            const float* __restrict__ aabb)
{
    const int tid   = threadIdx.x;
    const int lane  = tid & 31;
    const int t     = blockIdx.x * 256 + tid;            // 131072 threads
    const int warpW = t >> 5;                            // global warp id
    const int4* base = (const int4*)occ;

    int4 v[4];
    #pragma unroll
    for (int j = 0; j < 4; j++)
        v[j] = __ldcs(base + (warpW << 7) + (j << 5) + lane);

    // per-ray AABB intersection (threads 0..16383), bit-identical to the
    // sequence previously run by every sampler thread
    if (t < N_RAYS) {
        const float ox = rays_o[t * 3 + 0];
        const float oy = rays_o[t * 3 + 1];
        const float oz = rays_o[t * 3 + 2];
        const float dx = rays_d[t * 3 + 0];
        const float dy = rays_d[t * 3 + 1];
        const float dz = rays_d[t * 3 + 2];
        const float a0x = aabb[0], a0y = aabb[1], a0z = aabb[2];
        const float a1x = aabb[3], a1y = aabb[4], a1z = aabb[5];

        const float sdx = (fabsf(dx) > 1e-10f) ? dx : 1e-10f;
        const float sdy = (fabsf(dy) > 1e-10f) ? dy : 1e-10f;
        const float sdz = (fabsf(dz) > 1e-10f) ? dz : 1e-10f;
        const float ix_ = __fdiv_rn(1.0f, sdx);
        const float iy_ = __fdiv_rn(1.0f, sdy);
        const float iz_ = __fdiv_rn(1.0f, sdz);

        const float t0x = __fmul_rn(__fsub_rn(a0x, ox), ix_);
        const float t1x = __fmul_rn(__fsub_rn(a1x, ox), ix_);
        const float t0y = __fmul_rn(__fsub_rn(a0y, oy), iy_);
        const float t1y = __fmul_rn(__fsub_rn(a1y, oy), iy_);
        const float t0z = __fmul_rn(__fsub_rn(a0z, oz), iz_);
        const float t1z = __fmul_rn(__fsub_rn(a1z, oz), iz_);

        const float tmin = fmaxf(fmaxf(fmaxf(fminf(t0x, t1x), fminf(t0y, t1y)),
                                       fminf(t0z, t1z)), NEAR_F);
        const float tmax = fminf(fminf(fminf(fmaxf(t0x, t1x), fmaxf(t0y, t1y)),
                                       fmaxf(t0z, t1z)), FAR_F);
        g_tminmax[t] = make_float2(tmin, tmax);
    }

    #pragma unroll
    for (int j = 0; j < 4; j++) {
        const unsigned b0 = __ballot_sync(0xFFFFFFFFu, v[j].x != 0);
        const unsigned b1 = __ballot_sync(0xFFFFFFFFu, v[j].y != 0);
        const unsigned b2 = __ballot_sync(0xFFFFFFFFu, v[j].z != 0);
        const unsigned b3 = __ballot_sync(0xFFFFFFFFu, v[j].w != 0);
        if (lane < 4) {
            const int sh = lane << 3;
            const unsigned w = ((b0 >> sh) & 0xFFu)
                             | (((b1 >> sh) & 0xFFu) << 8)
                             | (((b2 >> sh) & 0xFFu) << 16)
                             | (((b3 >> sh) & 0xFFu) << 24);
            g_bits[(warpW << 4) + (j << 2) + lane] = w;
        }
    }

    if (blockIdx.x == 0 && tid < SCAN_BLOCKS)
        g_partials[tid] = 0;
}

// 256 threads/block, 2 rays/block, 128 threads/ray, 4 steps/thread.
__global__ void __launch_bounds__(256)
sampler_kernel(const float* __restrict__ rays_o,
               const float* __restrict__ rays_d,
               const float* __restrict__ aabb,
               float* __restrict__ out)
{
    const int tid = threadIdx.x;
    const int ray = blockIdx.x * 2 + (tid >> 7);
    const int q   = tid & 127;          // quad index within ray
    const int s0  = q << 2;             // first step of this thread's quad

    const float ox = rays_o[ray * 3 + 0];
    const float oy = rays_o[ray * 3 + 1];
    const float oz = rays_o[ray * 3 + 2];
    const float dx = rays_d[ray * 3 + 0];
    const float dy = rays_d[ray * 3 + 1];
    const float dz = rays_d[ray * 3 + 2];

    const float a0x = aabb[0], a0y = aabb[1], a0z = aabb[2];
    const float a1x = aabb[3], a1y = aabb[4], a1z = aabb[5];

    // precomputed per-ray intersection (L1 broadcast: 128 threads same addr)
    const float2 tm = g_tminmax[ray];
    const float tmin = tm.x, tmax = tm.y;

    const float ex = __fsub_rn(a1x, a0x);
    const float ey = __fsub_rn(a1y, a0y);
    const float ez = __fsub_rn(a1z, a0z);
    const float STEPF = step_size();

    float st[4], en[4], m[4];
    float sx[4], sy[4], sz[4];
    bool  valid[4];
    int   occ_idx[4];
    bool  pre[4];

    // Pass 1a: positions
    float nx[4], ny[4], nz[4];
    #pragma unroll
    for (int k = 0; k < 4; k++) {
        const int step = s0 + k;
        st[k] = __fadd_rn(NEAR_F, __fmul_rn((float)step,       STEPF));
        en[k] = __fadd_rn(NEAR_F, __fmul_rn((float)(step + 1), STEPF));
        const float mid = __fmul_rn(0.5f, __fadd_rn(st[k], en[k]));
        nx[k] = __fsub_rn(__fadd_rn(ox, __fmul_rn(dx, mid)), a0x);
        ny[k] = __fsub_rn(__fadd_rn(oy, __fmul_rn(dy, mid)), a0y);
        nz[k] = __fsub_rn(__fadd_rn(oz, __fmul_rn(dz, mid)), a0z);
    }

    // Pass 1b: scale = n / extent; pow2 extents -> exact multiply path
    if (is_pow2f(ex) && is_pow2f(ey) && is_pow2f(ez)) {
        const float ivx = __fdiv_rn(1.0f, ex);   // exact
        const float ivy = __fdiv_rn(1.0f, ey);
        const float ivz = __fdiv_rn(1.0f, ez);
        #pragma unroll
        for (int k = 0; k < 4; k++) {
            sx[k] = __fmul_rn(nx[k], ivx);
            sy[k] = __fmul_rn(ny[k], ivy);
            sz[k] = __fmul_rn(nz[k], ivz);
        }
    } else {
        #pragma unroll
        for (int k = 0; k < 4; k++) {
            sx[k] = __fdiv_rn(nx[k], ex);
            sy[k] = __fdiv_rn(ny[k], ey);
            sz[k] = __fdiv_rn(nz[k], ez);
        }
    }

    // Pass 1c: predicates + voxel indices
    #pragma unroll
    for (int k = 0; k < 4; k++) {
        const bool inside = (sx[k] >= 0.0f) && (sx[k] < 1.0f) &&
                            (sy[k] >= 0.0f) && (sy[k] < 1.0f) &&
                            (sz[k] >= 0.0f) && (sz[k] < 1.0f);
        int gx = (int)__fmul_rn(sx[k], (float)GRID_R);
        int gy = (int)__fmul_rn(sy[k], (float)GRID_R);
        int gz = (int)__fmul_rn(sz[k], (float)GRID_R);
        gx = min(max(gx, 0), GRID_R - 1);
        gy = min(max(gy, 0), GRID_R - 1);
        gz = min(max(gz, 0), GRID_R - 1);
        occ_idx[k] = (gx << 14) + (gy << 7) + gz;
        pre[k] = (st[k] >= tmin) && (en[k] <= tmax) && inside;
    }

    // Pass 2: 4 independent bit-grid lookups (256KB array, L1-warm)
    unsigned wv[4];
    #pragma unroll
    for (int k = 0; k < 4; k++) wv[k] = g_bits[occ_idx[k] >> 5];
    int cnt = 0;
    #pragma unroll
    for (int k = 0; k < 4; k++) {
        const int bit = ((occ_idx[k] & 3) << 3) | ((occ_idx[k] >> 2) & 7);
        valid[k] = pre[k] && ((wv[k] >> bit) & 1u);
        m[k] = valid[k] ? 1.0f : 0.0f;
        cnt += valid[k] ? 1 : 0;
    }

    const int seg = (ray << 9) + s0;           // multiple of 4

    // --- vectorized streaming stores ---
    const float rif = (float)ray;

    __stcs((float4*)(out + OFF_S + seg),
           make_float4(valid[0] ? st[0] : 0.0f, valid[1] ? st[1] : 0.0f,
                       valid[2] ? st[2] : 0.0f, valid[3] ? st[3] : 0.0f));
    __stcs((float4*)(out + OFF_E + seg),
           make_float4(valid[0] ? en[0] : 0.0f, valid[1] ? en[1] : 0.0f,
                       valid[2] ? en[2] : 0.0f, valid[3] ? en[3] : 0.0f));
    __stcs((float4*)(out + OFF_RI + seg), make_float4(rif, rif, rif, rif));
    __stcs((float4*)(out + OFF_MASK + seg), make_float4(m[0], m[1], m[2], m[3]));

    {
        const float x0 = __fmul_rn(ox, m[0]), y0 = __fmul_rn(oy, m[0]), z0 = __fmul_rn(oz, m[0]);
        const float x1 = __fmul_rn(ox, m[1]), y1 = __fmul_rn(oy, m[1]), z1 = __fmul_rn(oz, m[1]);
        const float x2 = __fmul_rn(ox, m[2]), y2 = __fmul_rn(oy, m[2]), z2 = __fmul_rn(oz, m[2]);
        const float x3 = __fmul_rn(ox, m[3]), y3 = __fmul_rn(oy, m[3]), z3 = __fmul_rn(oz, m[3]);
        float* ob = out + OFF_ORIG + seg * 3;
        __stcs((float4*)(ob + 0), make_float4(x0, y0, z0, x1));
        __stcs((float4*)(ob + 4), make_float4(y1, z1, x2, y2));
        __stcs((float4*)(ob + 8), make_float4(z2, x3, y3, z3));
    }
    {
        const float x0 = __fmul_rn(dx, m[0]), y0 = __fmul_rn(dy, m[0]), z0 = __fmul_rn(dz, m[0]);
        const float x1 = __fmul_rn(dx, m[1]), y1 = __fmul_rn(dy, m[1]), z1 = __fmul_rn(dz, m[1]);
        const float x2 = __fmul_rn(dx, m[2]), y2 = __fmul_rn(dy, m[2]), z2 = __fmul_rn(dz, m[2]);
        const float x3 = __fmul_rn(dx, m[3]), y3 = __fmul_rn(dy, m[3]), z3 = __fmul_rn(dz, m[3]);
        float* db = out + OFF_DIR + seg * 3;
        __stcs((float4*)(db + 0), make_float4(x0, y0, z0, x1));
        __stcs((float4*)(db + 4), make_float4(y1, z1, x2, y2));
        __stcs((float4*)(db + 8), make_float4(z2, x3, y3, z3));
    }

    // --- per-ray count: warp reduce + smem combine (4 warps per ray) ---
    const int wsum = __reduce_add_sync(0xFFFFFFFFu, cnt);
    __shared__ int ws[8];
    if ((tid & 31) == 0) ws[tid >> 5] = wsum;
    __syncthreads();
    if (q == 0) {
        const int b = (tid >> 7) * 4;
        const int c = ws[b] + ws[b + 1] + ws[b + 2] + ws[b + 3];
        g_counts[ray] = c;
        atomicAdd(&g_partials[ray >> 8], c);   // deterministic int sum
    }
}

// Final scan: 64 blocks x 256 threads, 1 ray/thread.
__global__ void __launch_bounds__(256)
scan_kernel(float* __restrict__ out)
{
    const int b    = blockIdx.x;
    const int tid  = threadIdx.x;
    const int lane = tid & 31;
    const int wid  = tid >> 5;          // 8 warps

    __shared__ int sh[8];
    __shared__ int s_pre;

    if (wid == 0) {
        int p = 0;
        if (lane      < b) p += g_partials[lane];
        if (lane + 32 < b) p += g_partials[lane + 32];
        p = __reduce_add_sync(0xFFFFFFFFu, p);
        if (lane == 0) s_pre = p;
    }

    const int ray = b * 256 + tid;
    const int cnt = g_counts[ray];

    int inc = cnt;
    #pragma unroll
    for (int d = 1; d < 32; d <<= 1) {
        int n = __shfl_up_sync(0xFFFFFFFFu, inc, d);
        if (lane >= d) inc += n;
    }
    if (lane == 31) sh[wid] = inc;
    __syncthreads();
    int woff = 0;
    #pragma unroll
    for (int i = 0; i < 8; i++) woff += (i < wid) ? sh[i] : 0;

    const int offset = s_pre + woff + (inc - cnt);   // exclusive

    *(float2*)(out + OFF_PK + ray * 2) = make_float2((float)offset, (float)cnt);
}

extern "C" void kernel_launch(void* const* d_in, const int* in_sizes, int n_in,
                              void* d_out, int out_size)
{
    const float* rays_o = (const float*)d_in[0];
    const float* rays_d = (const float*)d_in[1];
    const float* aabb   = (const float*)d_in[2];
    const int*   occ    = (const int*)  d_in[3];
    float* out = (float*)d_out;

    pack_kernel<<<N_VOXELS / 16 / 256, 256>>>(occ, rays_o, rays_d, aabb);
    sampler_kernel<<<N_RAYS / 2, 256>>>(rays_o, rays_d, aabb, out);
    scan_kernel<<<SCAN_BLOCKS, 256>>>(out);
}

// round 16
// speedup vs baseline: 1.1229x; 1.0092x over previous
#include <cuda_runtime.h>
#include <cuda_bf16.h>
#include <cstdint>

// ----------------------------------------------------------------------------
// VolumetricSampler: 16384 rays x 512 steps occupancy-grid sampling.
// Round 15: ballot-free pack — one bit-grid word per thread, 8 coalesced
// __ldcs int4 loads (MLP=8), pure-ALU nibble assembly. Bit mapping chosen so
// pack needs no cross-lane ops:
//   v = (W<<10)|(j<<7)|(lane<<2)|c  ->  word = (W<<5)|lane, bit = (j<<2)|c
//   lookup: word = ((v>>5)&~31)|((v>>2)&31), bit = ((v>>5)&28)|(v&3)
// Sampler (bit grid + hoisted tmin/tmax + pow2 multiply path) and scan
// unchanged. All __f*_rn predicate math frozen (rel_err 0.0 since R2).
//
// Output layout (float32):
//   origins     [8388608, 3]  -> [0,        25165824)
//   dirs        [8388608, 3]  -> [25165824, 50331648)
//   s_flat      [8388608]     -> [50331648, 58720256)
//   e_flat      [8388608]     -> [58720256, 67108864)
//   packed_info [16384, 2]    -> [67108864, 67141632)
//   ray_indices [8388608]     -> [67141632, 75530240)
//   mask        [8388608]     -> [75530240, 83918848)
// ----------------------------------------------------------------------------

#define N_RAYS     16384
#define MAX_STEPS  512
#define GRID_R     128
#define NEAR_F     0.05f
#define FAR_F      3.0f

static __device__ __forceinline__ float step_size() {
    return (float)((3.0 - 0.05) / 512.0);   // fp32-rounded STEP, matches jnp
}

#define OFF_ORIG   0
#define OFF_DIR    25165824
#define OFF_S      50331648
#define OFF_E      58720256
#define OFF_PK     67108864
#define OFF_RI     67141632
#define OFF_MASK   75530240

#define N_VOXELS   (GRID_R * GRID_R * GRID_R)   // 2,097,152
#define N_WORDS    (N_VOXELS / 32)              // 65,536
#define SCAN_BLOCKS 64

__device__ __align__(16) int      g_counts[N_RAYS];
__device__ __align__(16) int      g_partials[SCAN_BLOCKS];
__device__ __align__(16) unsigned g_bits[N_WORDS];
__device__ __align__(16) float2   g_tminmax[N_RAYS];

// exact power of two (positive, normal): mantissa bits all zero
static __device__ __forceinline__ bool is_pow2f(float e) {
    const unsigned u = __float_as_uint(e);
    return ((u & 0x007FFFFFu) == 0u) && e > 0.0f;
}

// --- prep: one bit-grid word per thread (8 coalesced int4 loads, MLP=8)
//     + per-ray tmin/tmax + partials zeroing. 65536 threads, 256 blocks. ---
__global__ void __launch_bounds__(256)
pack_kernel(const int* __restrict__ occ,
            const float* __restrict__ rays_o,
            const float* __restrict__ rays_d,
            const float* __restrict__ aabb)
{
    const int w    = blockIdx.x * 256 + threadIdx.x;   // word index 0..65535
    const int W    = w >> 5;                            // warp block
    const int lane = w & 31;
    const int4* base = (const int4*)occ + (W << 8) + lane;

    // 8 independent coalesced loads (warp round j reads int4s W*256+j*32+..)
    int4 v[8];
    #pragma unroll
    for (int j = 0; j < 8; j++)
        v[j] = __ldcs(base + (j << 5));

    unsigned bits = 0;
    #pragma unroll
    for (int j = 0; j < 8; j++) {
        unsigned nib = (v[j].x != 0 ? 1u : 0u)
                     | (v[j].y != 0 ? 2u : 0u)
                     | (v[j].z != 0 ? 4u : 0u)
                     | (v[j].w != 0 ? 8u : 0u);
        bits |= nib << (j << 2);
    }
    g_bits[w] = bits;

    // per-ray AABB intersection (threads 0..16383)
    if (w < N_RAYS) {
        const float ox = rays_o[w * 3 + 0];
        const float oy = rays_o[w * 3 + 1];
        const float oz = rays_o[w * 3 + 2];
        const float dx = rays_d[w * 3 + 0];
        const float dy = rays_d[w * 3 + 1];
        const float dz = rays_d[w * 3 + 2];
        const float a0x = aabb[0], a0y = aabb[1], a0z = aabb[2];
        const float a1x = aabb[3], a1y = aabb[4], a1z = aabb[5];

        const float sdx = (fabsf(dx) > 1e-10f) ? dx : 1e-10f;
        const float sdy = (fabsf(dy) > 1e-10f) ? dy : 1e-10f;
        const float sdz = (fabsf(dz) > 1e-10f) ? dz : 1e-10f;
        const float ix_ = __fdiv_rn(1.0f, sdx);
        const float iy_ = __fdiv_rn(1.0f, sdy);
        const float iz_ = __fdiv_rn(1.0f, sdz);

        const float t0x = __fmul_rn(__fsub_rn(a0x, ox), ix_);
        const float t1x = __fmul_rn(__fsub_rn(a1x, ox), ix_);
        const float t0y = __fmul_rn(__fsub_rn(a0y, oy), iy_);
        const float t1y = __fmul_rn(__fsub_rn(a1y, oy), iy_);
        const float t0z = __fmul_rn(__fsub_rn(a0z, oz), iz_);
        const float t1z = __fmul_rn(__fsub_rn(a1z, oz), iz_);

        const float tmin = fmaxf(fmaxf(fmaxf(fminf(t0x, t1x), fminf(t0y, t1y)),
                                       fminf(t0z, t1z)), NEAR_F);
        const float tmax = fminf(fminf(fminf(fmaxf(t0x, t1x), fmaxf(t0y, t1y)),
                                       fmaxf(t0z, t1z)), FAR_F);
        g_tminmax[w] = make_float2(tmin, tmax);
    }

    if (blockIdx.x == 0 && threadIdx.x < SCAN_BLOCKS)
        g_partials[threadIdx.x] = 0;
}

// 256 threads/block, 2 rays/block, 128 threads/ray, 4 steps/thread.
__global__ void __launch_bounds__(256)
sampler_kernel(const float* __restrict__ rays_o,
               const float* __restrict__ rays_d,
               const float* __restrict__ aabb,
               float* __restrict__ out)
{
    const int tid = threadIdx.x;
    const int ray = blockIdx.x * 2 + (tid >> 7);
    const int q   = tid & 127;          // quad index within ray
    const int s0  = q << 2;             // first step of this thread's quad

    const float ox = rays_o[ray * 3 + 0];
    const float oy = rays_o[ray * 3 + 1];
    const float oz = rays_o[ray * 3 + 2];
    const float dx = rays_d[ray * 3 + 0];
    const float dy = rays_d[ray * 3 + 1];
    const float dz = rays_d[ray * 3 + 2];

    const float a0x = aabb[0], a0y = aabb[1], a0z = aabb[2];
    const float a1x = aabb[3], a1y = aabb[4], a1z = aabb[5];

    // precomputed per-ray intersection (L1 broadcast)
    const float2 tm = g_tminmax[ray];
    const float tmin = tm.x, tmax = tm.y;

    const float ex = __fsub_rn(a1x, a0x);
    const float ey = __fsub_rn(a1y, a0y);
    const float ez = __fsub_rn(a1z, a0z);
    const float STEPF = step_size();

    float st[4], en[4], m[4];
    float sx[4], sy[4], sz[4];
    bool  valid[4];
    int   occ_idx[4];
    bool  pre[4];

    // Pass 1a: positions
    float nx[4], ny[4], nz[4];
    #pragma unroll
    for (int k = 0; k < 4; k++) {
        const int step = s0 + k;
        st[k] = __fadd_rn(NEAR_F, __fmul_rn((float)step,       STEPF));
        en[k] = __fadd_rn(NEAR_F, __fmul_rn((float)(step + 1), STEPF));
        const float mid = __fmul_rn(0.5f, __fadd_rn(st[k], en[k]));
        nx[k] = __fsub_rn(__fadd_rn(ox, __fmul_rn(dx, mid)), a0x);
        ny[k] = __fsub_rn(__fadd_rn(oy, __fmul_rn(dy, mid)), a0y);
        nz[k] = __fsub_rn(__fadd_rn(oz, __fmul_rn(dz, mid)), a0z);
    }

    // Pass 1b: scale = n / extent; pow2 extents -> exact multiply path
    if (is_pow2f(ex) && is_pow2f(ey) && is_pow2f(ez)) {
        const float ivx = __fdiv_rn(1.0f, ex);   // exact
        const float ivy = __fdiv_rn(1.0f, ey);
        const float ivz = __fdiv_rn(1.0f, ez);
        #pragma unroll
        for (int k = 0; k < 4; k++) {
            sx[k] = __fmul_rn(nx[k], ivx);
            sy[k] = __fmul_rn(ny[k], ivy);
            sz[k] = __fmul_rn(nz[k], ivz);
        }
    } else {
        #pragma unroll
        for (int k = 0; k < 4; k++) {
            sx[k] = __fdiv_rn(nx[k], ex);
            sy[k] = __fdiv_rn(ny[k], ey);
            sz[k] = __fdiv_rn(nz[k], ez);
        }
    }

    // Pass 1c: predicates + voxel indices
    #pragma unroll
    for (int k = 0; k < 4; k++) {
        const bool inside = (sx[k] >= 0.0f) && (sx[k] < 1.0f) &&
                            (sy[k] >= 0.0f) && (sy[k] < 1.0f) &&
                            (sz[k] >= 0.0f) && (sz[k] < 1.0f);
        int gx = (int)__fmul_rn(sx[k], (float)GRID_R);
        int gy = (int)__fmul_rn(sy[k], (float)GRID_R);
        int gz = (int)__fmul_rn(sz[k], (float)GRID_R);
        gx = min(max(gx, 0), GRID_R - 1);
        gy = min(max(gy, 0), GRID_R - 1);
        gz = min(max(gz, 0), GRID_R - 1);
        occ_idx[k] = (gx << 14) + (gy << 7) + gz;
        pre[k] = (st[k] >= tmin) && (en[k] <= tmax) && inside;
    }

    // Pass 2: 4 independent bit-grid lookups (256KB array, L1-warm)
    // word = ((v>>5) & ~31) | ((v>>2) & 31), bit = ((v>>5) & 28) | (v & 3)
    unsigned wv[4];
    #pragma unroll
    for (int k = 0; k < 4; k++) {
        const int u = occ_idx[k] >> 5;
        wv[k] = g_bits[(u & ~31) | ((occ_idx[k] >> 2) & 31)];
    }
    int cnt = 0;
    #pragma unroll
    for (int k = 0; k < 4; k++) {
        const int bit = ((occ_idx[k] >> 5) & 28) | (occ_idx[k] & 3);
        valid[k] = pre[k] && ((wv[k] >> bit) & 1u);
        m[k] = valid[k] ? 1.0f : 0.0f;
        cnt += valid[k] ? 1 : 0;
    }

    const int seg = (ray << 9) + s0;           // multiple of 4

    // --- vectorized streaming stores ---
    const float rif = (float)ray;

    __stcs((float4*)(out + OFF_S + seg),
           make_float4(valid[0] ? st[0] : 0.0f, valid[1] ? st[1] : 0.0f,
                       valid[2] ? st[2] : 0.0f, valid[3] ? st[3] : 0.0f));
    __stcs((float4*)(out + OFF_E + seg),
           make_float4(valid[0] ? en[0] : 0.0f, valid[1] ? en[1] : 0.0f,
                       valid[2] ? en[2] : 0.0f, valid[3] ? en[3] : 0.0f));
    __stcs((float4*)(out + OFF_RI + seg), make_float4(rif, rif, rif, rif));
    __stcs((float4*)(out + OFF_MASK + seg), make_float4(m[0], m[1], m[2], m[3]));

    {
        const float x0 = __fmul_rn(ox, m[0]), y0 = __fmul_rn(oy, m[0]), z0 = __fmul_rn(oz, m[0]);
        const float x1 = __fmul_rn(ox, m[1]), y1 = __fmul_rn(oy, m[1]), z1 = __fmul_rn(oz, m[1]);
        const float x2 = __fmul_rn(ox, m[2]), y2 = __fmul_rn(oy, m[2]), z2 = __fmul_rn(oz, m[2]);
        const float x3 = __fmul_rn(ox, m[3]), y3 = __fmul_rn(oy, m[3]), z3 = __fmul_rn(oz, m[3]);
        float* ob = out + OFF_ORIG + seg * 3;
        __stcs((float4*)(ob + 0), make_float4(x0, y0, z0, x1));
        __stcs((float4*)(ob + 4), make_float4(y1, z1, x2, y2));
        __stcs((float4*)(ob + 8), make_float4(z2, x3, y3, z3));
    }
    {
        const float x0 = __fmul_rn(dx, m[0]), y0 = __fmul_rn(dy, m[0]), z0 = __fmul_rn(dz, m[0]);
        const float x1 = __fmul_rn(dx, m[1]), y1 = __fmul_rn(dy, m[1]), z1 = __fmul_rn(dz, m[1]);
        const float x2 = __fmul_rn(dx, m[2]), y2 = __fmul_rn(dy, m[2]), z2 = __fmul_rn(dz, m[2]);
        const float x3 = __fmul_rn(dx, m[3]), y3 = __fmul_rn(dy, m[3]), z3 = __fmul_rn(dz, m[3]);
        float* db = out + OFF_DIR + seg * 3;
        __stcs((float4*)(db + 0), make_float4(x0, y0, z0, x1));
        __stcs((float4*)(db + 4), make_float4(y1, z1, x2, y2));
        __stcs((float4*)(db + 8), make_float4(z2, x3, y3, z3));
    }

    // --- per-ray count: warp reduce + smem combine (4 warps per ray) ---
    const int wsum = __reduce_add_sync(0xFFFFFFFFu, cnt);
    __shared__ int ws[8];
    if ((tid & 31) == 0) ws[tid >> 5] = wsum;
    __syncthreads();
    if (q == 0) {
        const int b = (tid >> 7) * 4;
        const int c = ws[b] + ws[b + 1] + ws[b + 2] + ws[b + 3];
        g_counts[ray] = c;
        atomicAdd(&g_partials[ray >> 8], c);   // deterministic int sum
    }
}

// Final scan: 64 blocks x 256 threads, 1 ray/thread.
__global__ void __launch_bounds__(256)
scan_kernel(float* __restrict__ out)
{
    const int b    = blockIdx.x;
    const int tid  = threadIdx.x;
    const int lane = tid & 31;
    const int wid  = tid >> 5;          // 8 warps

    __shared__ int sh[8];
    __shared__ int s_pre;

    if (wid == 0) {
        int p = 0;
        if (lane      < b) p += g_partials[lane];
        if (lane + 32 < b) p += g_partials[lane + 32];
        p = __reduce_add_sync(0xFFFFFFFFu, p);
        if (lane == 0) s_pre = p;
    }

    const int ray = b * 256 + tid;
    const int cnt = g_counts[ray];

    int inc = cnt;
    #pragma unroll
    for (int d = 1; d < 32; d <<= 1) {
        int n = __shfl_up_sync(0xFFFFFFFFu, inc, d);
        if (lane >= d) inc += n;
    }
    if (lane == 31) sh[wid] = inc;
    __syncthreads();
    int woff = 0;
    #pragma unroll
    for (int i = 0; i < 8; i++) woff += (i < wid) ? sh[i] : 0;

    const int offset = s_pre + woff + (inc - cnt);   // exclusive

    *(float2*)(out + OFF_PK + ray * 2) = make_float2((float)offset, (float)cnt);
}

extern "C" void kernel_launch(void* const* d_in, const int* in_sizes, int n_in,
                              void* d_out, int out_size)
{
    const float* rays_o = (const float*)d_in[0];
    const float* rays_d = (const float*)d_in[1];
    const float* aabb   = (const float*)d_in[2];
    const int*   occ    = (const int*)  d_in[3];
    float* out = (float*)d_out;

    pack_kernel<<<N_WORDS / 256, 256>>>(occ, rays_o, rays_d, aabb);
    sampler_kernel<<<N_RAYS / 2, 256>>>(rays_o, rays_d, aabb, out);
    scan_kernel<<<SCAN_BLOCKS, 256>>>(out);
}